// round 9
// baseline (speedup 1.0000x reference)
#include <cuda_runtime.h>

#define RR 8
#define BB 8
#define LL 2048
#define PP 16384
#define HQ 32
#define HKV 8
#define GG 4
#define DD 128
#define NSPLIT 16
#define CHUNK (LL / NSPLIT)   // 128
#define TILE 16
#define NSTAGE 3
#define RS (RR * NSPLIT)      // 128 partials per (b, hq)
#define SCALE_F 0.08838834764831845f
#define NEGINF -1.0e30f
#define HD (HKV * DD)         // 1024 floats per page row

// Dynamic smem layout (float offsets):
//   [0     .. 6144)  Ks[3][TILE*DD]   (XOR-swizzled chunks)
//   [6144  .. 12288) Vs[3][TILE*DD]   (linear)
//   [12288 .. 12416) pg_all (128 ints)
//   [12416 .. 12928) q_s (4 heads x 128)
#define SM_K(s)   (smf + (s) * (TILE * DD))
#define SM_V(s)   (smf + 6144 + (s) * (TILE * DD))
#define SM_PG     ((int*)(smf + 12288))
#define SM_Q      (smf + 12416)
#define SMEM_BYTES (12928 * 4)

// Scratch for split-KV partials (device globals; no runtime allocation).
__device__ float g_po[RS * BB * HQ * DD];   // normalized partial O (~16.8MB)
__device__ float g_plse[RS * BB * HQ];      // partial LSE

// Stage one 16-token tile of K and V (8KB + 8KB) via cp.async.
// K rows are chunk-swizzled: logical 16B-chunk j of token t lands at
// physical slot j ^ (t & 7), making Phase A's per-lane row reads
// bank-conflict-free.
__device__ __forceinline__ void stage_tile(float* smf, int tid, int nbase,
                                           int bufi,
                                           const float* __restrict__ kh,
                                           const float* __restrict__ vhh)
{
    const unsigned kd = (unsigned)__cvta_generic_to_shared(SM_K(bufi));
    const unsigned vd = (unsigned)__cvta_generic_to_shared(SM_V(bufi));
    #pragma unroll
    for (int i = 0; i < 4; ++i) {
        const int c   = i * 128 + tid;    // 0..511 chunk id (16B)
        const int tok = c >> 5;           // 0..15
        const int j   = c & 31;           // chunk within row
        const long prow = (long)SM_PG[nbase + tok] * HD;
        const unsigned kdst = kd + (unsigned)(((tok * DD) + ((j ^ (tok & 7)) << 2)) << 2);
        const unsigned vdst = vd + (unsigned)(((tok * DD) + (j << 2)) << 2);
        asm volatile("cp.async.cg.shared.global [%0], [%1], 16;\n"
                     :: "r"(kdst), "l"(kh + prow + (j << 2)));
        asm volatile("cp.async.cg.shared.global [%0], [%1], 16;\n"
                     :: "r"(vdst), "l"(vhh + prow + (j << 2)));
    }
}

__global__ void __launch_bounds__(128)
decode_kernel(const float* __restrict__ q,
              const float* __restrict__ kc,
              const float* __restrict__ vc,
              const int* __restrict__ lens,
              const int* __restrict__ bt)
{
    extern __shared__ float smf[];

    const int split = blockIdx.x;
    const int hkv   = blockIdx.y;
    const int rb    = blockIdx.z;          // r*BB + b
    const int r     = rb >> 3;
    const int b     = rb & 7;
    const int tid   = threadIdx.x;
    const int wid   = tid >> 5;            // warp == head (hkv*GG + wid)
    const int lane  = tid & 31;
    const int h     = lane >> 4;           // dim-half (0: dims 0-63, 1: 64-127)
    const int tok   = lane & 15;           // token within tile
    const int txor  = tok & 7;

    const int kv_len = lens[rb];
    const int start  = split * CHUNK;
    const int end    = min(start + CHUNK, kv_len);
    const int pbase  = ((r * NSPLIT + split) * BB + b) * HQ + hkv * GG;

    if (end <= start) {
        if (tid < GG)
            g_plse[pbase + tid] = NEGINF;
        return;
    }
    const int len    = end - start;                 // 1..128
    const int ntiles = (len + TILE - 1) / TILE;     // 1..8

    const int*   btb = bt + rb * LL + start;
    const float* kh  = kc + (long)r * PP * HD + hkv * DD;
    const float* vhh = vc + (long)r * PP * HD + hkv * DD;

    // ---- Preload all pages for this chunk + Q for the 4 heads.
    SM_PG[tid] = (tid < len) ? __ldg(btb + tid) : 0;
    {
        const float4* qb4 = (const float4*)(q + (b * HQ + hkv * GG) * DD);
        ((float4*)SM_Q)[tid] = qb4[tid];   // 4 heads x 128 = 128 float4s
    }
    __syncthreads();

    // ---- Prime pipeline: stage tile 0.
    stage_tile(smf, tid, 0, 0, kh, vhh);
    asm volatile("cp.async.commit_group;\n" ::: "memory");

    float4 acc = make_float4(0.f, 0.f, 0.f, 0.f);   // dims lane*4..+3, head wid
    float  m_run = NEGINF, l_run = 0.f;             // warp-uniform

    const float4* qv = (const float4*)SM_Q + wid * 32 + h * 16;

    for (int n = 0; n < ntiles; ++n) {
        const int buf   = n % NSTAGE;
        const int tbase = n * TILE;
        const int nt    = min(TILE, len - tbase);

        if (n + 1 < ntiles)
            stage_tile(smf, tid, tbase + TILE, (n + 1) % NSTAGE, kh, vhh);
        asm volatile("cp.async.commit_group;\n" ::: "memory");
        asm volatile("cp.async.wait_group 1;\n" ::: "memory");  // tile n ready
        __syncthreads();   // the only barrier per tile

        // ---- Phase A: score for token `tok`, head `wid`; this thread does
        //      dim-half h (16 chunks), joined with its partner by one SHFL.
        //      Physical slot h*16+(t^txor) holds LOGICAL chunk h*16+t, so it
        //      pairs with qv[t].  (R8 bug: paired with qv[t^txor].)
        const float* kb = SM_K(buf) + tok * DD;
        float4 a4 = make_float4(0.f, 0.f, 0.f, 0.f);
        #pragma unroll
        for (int t = 0; t < 16; ++t) {
            const float4 k4 = *(const float4*)(kb + ((h * 16 + (t ^ txor)) << 2));
            const float4 q4 = qv[t];
            a4.x += q4.x * k4.x; a4.y += q4.y * k4.y;
            a4.z += q4.z * k4.z; a4.w += q4.w * k4.w;
        }
        float s = (a4.x + a4.y) + (a4.z + a4.w);
        s += __shfl_xor_sync(0xffffffffu, s, 16);   // join the two halves
        s = (tok < nt) ? s * SCALE_F : NEGINF;

        // ---- Online softmax: fully warp-local (both halves redundant).
        float x = s;
        #pragma unroll
        for (int off = 8; off; off >>= 1)
            x = fmaxf(x, __shfl_xor_sync(0xffffffffu, x, off));
        const float mn  = fmaxf(m_run, x);
        const float scl = __expf(m_run - mn);
        m_run = mn;
        const float p = __expf(s - mn);             // 0 for invalid tokens
        float ps = p;
        #pragma unroll
        for (int off = 8; off; off >>= 1)
            ps += __shfl_xor_sync(0xffffffffu, ps, off);
        l_run = l_run * scl + ps;

        // ---- Rescale + P.V: thread owns dims lane*4..+3 of head wid.
        acc.x *= scl; acc.y *= scl; acc.z *= scl; acc.w *= scl;
        const float* Vb = SM_V(buf) + lane * 4;
        for (int j = 0; j < nt; ++j) {
            const float  pj = __shfl_sync(0xffffffffu, p, j);
            const float4 v4 = *(const float4*)(Vb + j * DD);
            acc.x += pj * v4.x; acc.y += pj * v4.y;
            acc.z += pj * v4.z; acc.w += pj * v4.w;
        }
        // No trailing barrier: ring has 3 stages, staging targets (n+1)%3,
        // slowest possible reader is in tile n-1 on (n-1)%3 -- disjoint.
    }

    // ---- Finalize: everything warp-local.
    const float li = 1.0f / fmaxf(l_run, 1e-30f);
    float4 o = make_float4(acc.x * li, acc.y * li, acc.z * li, acc.w * li);
    *(float4*)(&g_po[(pbase + wid) * DD + lane * 4]) = o;
    if (lane == 0)
        g_plse[pbase + wid] = m_run + __logf(fmaxf(l_run, 1e-30f));
}

#define CTHREADS 512
#define NSLICE 4
#define PER_SLICE (RS / NSLICE)   // 32

__global__ void __launch_bounds__(CTHREADS)
combine_kernel(float* __restrict__ out)
{
    const int bh  = blockIdx.x;     // b*HQ + hq
    const int tid = threadIdx.x;
    const int d   = tid & 127;      // output dim
    const int sl  = tid >> 7;       // slice 0..3

    __shared__ float lse_s[RS];
    __shared__ float accs[NSLICE][DD];
    __shared__ float wss[NSLICE];

    if (tid < RS)
        lse_s[tid] = g_plse[tid * (BB * HQ) + bh];
    __syncthreads();

    float gm = NEGINF;
    #pragma unroll
    for (int i = 0; i < RS; ++i)
        gm = fmaxf(gm, lse_s[i]);

    float acc = 0.f, ws = 0.f;
    #pragma unroll
    for (int t = 0; t < PER_SLICE; ++t) {
        const int   i   = sl * PER_SLICE + t;
        const float lse = lse_s[i];
        if (lse > -5.0e29f) {
            const float w = __expf(lse - gm);
            ws  += w;
            acc += w * __ldg(&g_po[(i * (BB * HQ) + bh) * DD + d]);
        }
    }
    accs[sl][d] = acc;
    if (d == 0) wss[sl] = ws;
    __syncthreads();

    if (sl == 0) {
        const float a  = accs[0][d] + accs[1][d] + accs[2][d] + accs[3][d];
        const float wt = wss[0] + wss[1] + wss[2] + wss[3];
        out[bh * DD + d] = a / fmaxf(wt, 1e-30f);
    }
}

extern "C" void kernel_launch(void* const* d_in, const int* in_sizes, int n_in,
                              void* d_out, int out_size)
{
    (void)in_sizes; (void)n_in; (void)out_size;
    const float* q    = (const float*)d_in[0];
    const float* kc   = (const float*)d_in[1];
    const float* vc   = (const float*)d_in[2];
    const int*   lens = (const int*)d_in[3];
    const int*   bt   = (const int*)d_in[4];

    cudaFuncSetAttribute(decode_kernel,
                         cudaFuncAttributeMaxDynamicSharedMemorySize, SMEM_BYTES);

    dim3 grid1(NSPLIT, HKV, RR * BB);
    decode_kernel<<<grid1, 128, SMEM_BYTES>>>(q, kc, vc, lens, bt);
    combine_kernel<<<BB * HQ, CTHREADS>>>((float*)d_out);
}

// round 10
// speedup vs baseline: 1.2299x; 1.2299x over previous
#include <cuda_runtime.h>

#define RR 8
#define BB 8
#define LL 2048
#define PP 16384
#define HQ 32
#define HKV 8
#define GG 4
#define DD 128
#define NSPLIT 16
#define CHUNK (LL / NSPLIT)   // 128
#define TILE 16
#define RS (RR * NSPLIT)      // 128 partials per (b, hq)
#define SCALE_F 0.08838834764831845f
#define NEGINF -1.0e30f
#define HD (HKV * DD)         // 1024 floats per page row

// Dynamic smem layout (float offsets):
//   [0    .. 4096)  Ks[2][TILE*DD]   (16KB)
//   [4096 .. 8192)  Vs[2][TILE*DD]   (16KB)
//   [8192 .. 8320)  pg_all (128 ints)
//   [8320 .. 8384)  s_s (TILE*4)
//   [8384 .. 8448)  p_s (TILE*4)
//   [8448 .. 8460)  sc, m_fin, l_fin
#define SM_K(s)   (smf + (s) * (TILE * DD))
#define SM_V(s)   (smf + 4096 + (s) * (TILE * DD))
#define SM_PG     ((int*)(smf + 8192))
#define SM_S      (smf + 8320)
#define SM_P      (smf + 8384)
#define SM_SC     (smf + 8448)
#define SM_MF     (smf + 8452)
#define SM_LF     (smf + 8456)
#define SMEM_BYTES (8460 * 4)

// Scratch for split-KV partials (device globals; no runtime allocation).
__device__ float g_po[RS * BB * HQ * DD];   // normalized partial O (~16.8MB)
__device__ float g_plse[RS * BB * HQ];      // partial LSE

// Stage one 16-token tile of K and V (8KB + 8KB) via cp.async.
// 512 chunks of 16B each stream; 4 K-chunks + 4 V-chunks per thread.
__device__ __forceinline__ void stage_tile(float* smf, int tid, int nbase,
                                           int bufi,
                                           const float* __restrict__ kh,
                                           const float* __restrict__ vhh)
{
    const unsigned kd = (unsigned)__cvta_generic_to_shared(SM_K(bufi));
    const unsigned vd = (unsigned)__cvta_generic_to_shared(SM_V(bufi));
    #pragma unroll
    for (int i = 0; i < 4; ++i) {
        const int c   = i * 128 + tid;    // 0..511 chunk id (16B)
        const int tok = c >> 5;           // 0..15
        const int off = (c & 31) << 2;    // float offset in row
        const long prow = (long)SM_PG[nbase + tok] * HD;
        const unsigned doff = (unsigned)((tok * DD + off) << 2);
        asm volatile("cp.async.cg.shared.global [%0], [%1], 16;\n"
                     :: "r"(kd + doff), "l"(kh + prow + off));
        asm volatile("cp.async.cg.shared.global [%0], [%1], 16;\n"
                     :: "r"(vd + doff), "l"(vhh + prow + off));
    }
}

__global__ void __launch_bounds__(128)
decode_kernel(const float* __restrict__ q,
              const float* __restrict__ kc,
              const float* __restrict__ vc,
              const int* __restrict__ lens,
              const int* __restrict__ bt)
{
    extern __shared__ float smf[];

    const int split = blockIdx.x;
    const int hkv   = blockIdx.y;
    const int rb    = blockIdx.z;          // r*BB + b
    const int r     = rb >> 3;
    const int b     = rb & 7;
    const int tid   = threadIdx.x;
    const int wid   = tid >> 5;            // 0..3  (warp == head for softmax)
    const int lane  = tid & 31;
    const int half  = lane >> 4;
    const int hl    = lane & 15;           // lane within half-warp
    const int hw    = wid * 2 + half;      // half-warp id 0..7

    const int kv_len = lens[rb];
    const int start  = split * CHUNK;
    const int end    = min(start + CHUNK, kv_len);
    const int pbase  = ((r * NSPLIT + split) * BB + b) * HQ + hkv * GG;

    if (end <= start) {
        if (tid < GG)
            g_plse[pbase + tid] = NEGINF;
        return;
    }
    const int len    = end - start;                 // 1..128
    const int ntiles = (len + TILE - 1) / TILE;     // 1..8

    // Q into registers: head g, dims hl*8 .. hl*8+7
    const float* qb = q + (b * HQ + hkv * GG) * DD + hl * 8;
    float4 q0[GG], q1[GG];
    #pragma unroll
    for (int g = 0; g < GG; ++g) {
        q0[g] = *(const float4*)(qb + g * DD);
        q1[g] = *(const float4*)(qb + g * DD + 4);
    }

    const int*   btb = bt + rb * LL + start;
    const float* kh  = kc + (long)r * PP * HD + hkv * DD;
    const float* vhh = vc + (long)r * PP * HD + hkv * DD;

    // ---- Preload all pages for this chunk (one volley, page 0 for invalid).
    SM_PG[tid] = (tid < len) ? __ldg(btb + tid) : 0;
    __syncthreads();

    // ---- Prime: stage tile 0.
    stage_tile(smf, tid, 0, 0, kh, vhh);
    asm volatile("cp.async.commit_group;\n" ::: "memory");

    float acc0 = 0.f, acc1 = 0.f, acc2 = 0.f, acc3 = 0.f;
    float m_run = NEGINF, l_run = 0.f;

    for (int n = 0; n < ntiles; ++n) {
        const int buf   = n & 1;
        const int tbase = n * TILE;
        const int nt    = min(TILE, len - tbase);

        if (n + 1 < ntiles)
            stage_tile(smf, tid, tbase + TILE, buf ^ 1, kh, vhh);
        asm volatile("cp.async.commit_group;\n" ::: "memory");
        asm volatile("cp.async.wait_group 1;\n" ::: "memory");  // tile n ready
        __syncthreads();

        // ---- Phase A: scores from smem K. Half-warp per token, 2 passes.
        const float* Kb = SM_K(buf);
        #pragma unroll
        for (int pass = 0; pass < 2; ++pass) {
            const int tt = pass * 8 + hw;                // token in tile
            const float* kr = Kb + tt * DD + hl * 8;
            const float4 k0 = *(const float4*)kr;
            const float4 k1 = *(const float4*)(kr + 4);

            float s0 = q0[0].x*k0.x + q0[0].y*k0.y + q0[0].z*k0.z + q0[0].w*k0.w
                     + q1[0].x*k1.x + q1[0].y*k1.y + q1[0].z*k1.z + q1[0].w*k1.w;
            float s1 = q0[1].x*k0.x + q0[1].y*k0.y + q0[1].z*k0.z + q0[1].w*k0.w
                     + q1[1].x*k1.x + q1[1].y*k1.y + q1[1].z*k1.z + q1[1].w*k1.w;
            float s2 = q0[2].x*k0.x + q0[2].y*k0.y + q0[2].z*k0.z + q0[2].w*k0.w
                     + q1[2].x*k1.x + q1[2].y*k1.y + q1[2].z*k1.z + q1[2].w*k1.w;
            float s3 = q0[3].x*k0.x + q0[3].y*k0.y + q0[3].z*k0.z + q0[3].w*k0.w
                     + q1[3].x*k1.x + q1[3].y*k1.y + q1[3].z*k1.z + q1[3].w*k1.w;

            #pragma unroll
            for (int off = 8; off; off >>= 1) {
                s0 += __shfl_xor_sync(0xffffffffu, s0, off);
                s1 += __shfl_xor_sync(0xffffffffu, s1, off);
                s2 += __shfl_xor_sync(0xffffffffu, s2, off);
                s3 += __shfl_xor_sync(0xffffffffu, s3, off);
            }
            if (hl == 0) {
                float4* s4 = (float4*)SM_S;
                s4[tt] = (tt < nt) ? make_float4(s0 * SCALE_F, s1 * SCALE_F,
                                                 s2 * SCALE_F, s3 * SCALE_F)
                                   : make_float4(NEGINF, NEGINF, NEGINF, NEGINF);
            }
        }
        __syncthreads();   // sync1: s_s ready

        // ---- Online softmax: warp `wid` owns head `wid`. TILE=16, so both
        //      16-lane halves hold duplicate values; half-reductions (offsets
        //      8..1) therefore produce the full, warp-uniform max and sum.
        {
            const float xa = SM_S[hl * 4 + wid];
            float x = xa;
            #pragma unroll
            for (int off = 8; off; off >>= 1)
                x = fmaxf(x, __shfl_xor_sync(0xffffffffu, x, off));
            const float mn  = fmaxf(m_run, x);
            const float scl = __expf(m_run - mn);
            m_run = mn;
            if (lane == 0) SM_SC[wid] = scl;
            const float pa = __expf(xa - mn);
            if (half == 0) SM_P[hl * 4 + wid] = pa;
            float ps = pa;
            #pragma unroll
            for (int off = 8; off; off >>= 1)
                ps += __shfl_xor_sync(0xffffffffu, ps, off);
            l_run = l_run * scl + ps;
        }
        __syncthreads();   // sync2: p_s / sc_s ready

        // ---- Rescale + Phase B: thread tid owns dim d = tid for all 4 heads.
        const float c0 = SM_SC[0], c1 = SM_SC[1], c2 = SM_SC[2], c3 = SM_SC[3];
        acc0 *= c0; acc1 *= c1; acc2 *= c2; acc3 *= c3;

        const float4* p4s = (const float4*)SM_P;
        const float*  Vb  = SM_V(buf) + tid;
        #pragma unroll 8
        for (int j = 0; j < nt; ++j) {
            const float4 p4 = p4s[j];
            const float  v  = Vb[j * DD];
            acc0 += p4.x * v; acc1 += p4.y * v;
            acc2 += p4.z * v; acc3 += p4.w * v;
        }
        // No trailing barrier: next iteration's post-wait __syncthreads covers
        // s_s/p_s WAR; K/V buffers are double-buffered.
    }

    if (lane == 0) { SM_MF[wid] = m_run; SM_LF[wid] = l_run; }
    __syncthreads();

    const float l0 = fmaxf(SM_LF[0], 1e-30f);
    const float l1 = fmaxf(SM_LF[1], 1e-30f);
    const float l2 = fmaxf(SM_LF[2], 1e-30f);
    const float l3 = fmaxf(SM_LF[3], 1e-30f);
    g_po[(pbase + 0) * DD + tid] = acc0 / l0;
    g_po[(pbase + 1) * DD + tid] = acc1 / l1;
    g_po[(pbase + 2) * DD + tid] = acc2 / l2;
    g_po[(pbase + 3) * DD + tid] = acc3 / l3;
    if (tid < GG)
        g_plse[pbase + tid] = SM_MF[tid] + __logf(fmaxf(SM_LF[tid], 1e-30f));
}

#define CTHREADS 512
#define NSLICE 4
#define PER_SLICE (RS / NSLICE)   // 32

__global__ void __launch_bounds__(CTHREADS)
combine_kernel(float* __restrict__ out)
{
    const int bh  = blockIdx.x;     // b*HQ + hq
    const int tid = threadIdx.x;
    const int d   = tid & 127;      // output dim
    const int sl  = tid >> 7;       // slice 0..3

    __shared__ float lse_s[RS];
    __shared__ float accs[NSLICE][DD];
    __shared__ float wss[NSLICE];

    if (tid < RS)
        lse_s[tid] = g_plse[tid * (BB * HQ) + bh];
    __syncthreads();

    float gm = NEGINF;
    #pragma unroll
    for (int i = 0; i < RS; ++i)
        gm = fmaxf(gm, lse_s[i]);

    float acc = 0.f, ws = 0.f;
    #pragma unroll
    for (int t = 0; t < PER_SLICE; ++t) {
        const int   i   = sl * PER_SLICE + t;
        const float lse = lse_s[i];
        if (lse > -5.0e29f) {
            const float w = __expf(lse - gm);
            ws  += w;
            acc += w * __ldg(&g_po[(i * (BB * HQ) + bh) * DD + d]);
        }
    }
    accs[sl][d] = acc;
    if (d == 0) wss[sl] = ws;
    __syncthreads();

    if (sl == 0) {
        const float a  = accs[0][d] + accs[1][d] + accs[2][d] + accs[3][d];
        const float wt = wss[0] + wss[1] + wss[2] + wss[3];
        out[bh * DD + d] = a / fmaxf(wt, 1e-30f);
    }
}

extern "C" void kernel_launch(void* const* d_in, const int* in_sizes, int n_in,
                              void* d_out, int out_size)
{
    (void)in_sizes; (void)n_in; (void)out_size;
    const float* q    = (const float*)d_in[0];
    const float* kc   = (const float*)d_in[1];
    const float* vc   = (const float*)d_in[2];
    const int*   lens = (const int*)d_in[3];
    const int*   bt   = (const int*)d_in[4];

    cudaFuncSetAttribute(decode_kernel,
                         cudaFuncAttributeMaxDynamicSharedMemorySize, SMEM_BYTES);

    dim3 grid1(NSPLIT, HKV, RR * BB);
    decode_kernel<<<grid1, 128, SMEM_BYTES>>>(q, kc, vc, lens, bt);
    combine_kernel<<<BB * HQ, CTHREADS>>>((float*)d_out);
}

// round 11
// speedup vs baseline: 1.3119x; 1.0667x over previous
#include <cuda_runtime.h>

#define RR 8
#define BB 8
#define LL 2048
#define PP 16384
#define HQ 32
#define HKV 8
#define GG 4
#define DD 128
#define NSPLIT 16
#define CHUNK (LL / NSPLIT)   // 128
#define TILE 16
#define RS (RR * NSPLIT)      // 128 partials per (b, hq)
#define SCALE_F 0.08838834764831845f
#define NEGINF -1.0e30f
#define HD (HKV * DD)         // 1024 floats per page row

// Dynamic smem layout (float offsets):
//   [0    .. 4096)  Ks[2][TILE*DD]   (16KB)
//   [4096 .. 8192)  Vs[2][TILE*DD]   (16KB)
//   [8192 .. 8320)  pg_all (128 ints)
//   [8320 .. 8384)  s_s (TILE*4)
//   [8384 .. 8448)  p_s (TILE*4)
//   [8448 .. 8460)  sc, m_fin, l_fin
#define SM_K(s)   (smf + (s) * (TILE * DD))
#define SM_V(s)   (smf + 4096 + (s) * (TILE * DD))
#define SM_PG     ((int*)(smf + 8192))
#define SM_S      (smf + 8320)
#define SM_P      (smf + 8384)
#define SM_SC     (smf + 8448)
#define SM_MF     (smf + 8452)
#define SM_LF     (smf + 8456)
#define SMEM_BYTES (8460 * 4)

// Scratch for split-KV partials (device globals; no runtime allocation).
__device__ float g_po[RS * BB * HQ * DD];   // normalized partial O (~16.8MB)
__device__ float g_plse[RS * BB * HQ];      // partial LSE

// Stage one 16-token tile of K and V (8KB + 8KB) via cp.async.
// 512 chunks of 16B each; 4 K-chunks + 4 V-chunks per thread.
__device__ __forceinline__ void stage_tile(float* smf, int tid, int nbase,
                                           int bufi,
                                           const float* __restrict__ kh,
                                           const float* __restrict__ vhh)
{
    const unsigned kd = (unsigned)__cvta_generic_to_shared(SM_K(bufi));
    const unsigned vd = (unsigned)__cvta_generic_to_shared(SM_V(bufi));
    #pragma unroll
    for (int i = 0; i < 4; ++i) {
        const int c   = i * 128 + tid;    // 0..511 chunk id (16B)
        const int tok = c >> 5;           // 0..15
        const int off = (c & 31) << 2;    // float offset in row
        const long prow = (long)SM_PG[nbase + tok] * HD;
        const unsigned doff = (unsigned)((tok * DD + off) << 2);
        asm volatile("cp.async.cg.shared.global [%0], [%1], 16;\n"
                     :: "r"(kd + doff), "l"(kh + prow + off));
        asm volatile("cp.async.cg.shared.global [%0], [%1], 16;\n"
                     :: "r"(vd + doff), "l"(vhh + prow + off));
    }
}

__global__ void __launch_bounds__(128)
decode_kernel(const float* __restrict__ q,
              const float* __restrict__ kc,
              const float* __restrict__ vc,
              const int* __restrict__ lens,
              const int* __restrict__ bt)
{
    extern __shared__ float smf[];

    const int split = blockIdx.x;
    const int hkv   = blockIdx.y;
    const int rb    = blockIdx.z;          // r*BB + b
    const int r     = rb >> 3;
    const int b     = rb & 7;
    const int tid   = threadIdx.x;
    const int wid   = tid >> 5;            // 0..3  (warp == head for softmax)
    const int lane  = tid & 31;
    const int half  = lane >> 4;
    const int hl    = lane & 15;           // lane within half-warp
    const int hw    = wid * 2 + half;      // half-warp id 0..7

    const int kv_len = lens[rb];
    const int start  = split * CHUNK;
    const int end    = min(start + CHUNK, kv_len);
    const int pbase  = ((r * NSPLIT + split) * BB + b) * HQ + hkv * GG;

    if (end <= start) {
        if (tid < GG)
            g_plse[pbase + tid] = NEGINF;
        return;
    }
    const int len    = end - start;                 // 1..128
    const int ntiles = (len + TILE - 1) / TILE;     // 1..8

    // Q into registers: head g, dims hl*4..+3 (lo) and 64+hl*4..+3 (hi).
    // This mapping makes Phase A's LDS.128s quarter-warp contiguous (128B)
    // -> bank-conflict-free (the old hl*8 mapping was 2-way conflicted).
    const float* qb = q + (b * HQ + hkv * GG) * DD + hl * 4;
    float4 q0[GG], q1[GG];
    #pragma unroll
    for (int g = 0; g < GG; ++g) {
        q0[g] = *(const float4*)(qb + g * DD);
        q1[g] = *(const float4*)(qb + g * DD + 64);
    }

    const int*   btb = bt + rb * LL + start;
    const float* kh  = kc + (long)r * PP * HD + hkv * DD;
    const float* vhh = vc + (long)r * PP * HD + hkv * DD;

    // ---- Preload all pages for this chunk (one volley, page 0 for invalid).
    SM_PG[tid] = (tid < len) ? __ldg(btb + tid) : 0;
    __syncthreads();

    // ---- Prime: stage tile 0.
    stage_tile(smf, tid, 0, 0, kh, vhh);
    asm volatile("cp.async.commit_group;\n" ::: "memory");

    float acc0 = 0.f, acc1 = 0.f, acc2 = 0.f, acc3 = 0.f;
    float m_run = NEGINF, l_run = 0.f;

    for (int n = 0; n < ntiles; ++n) {
        const int buf   = n & 1;
        const int tbase = n * TILE;
        const int nt    = min(TILE, len - tbase);

        asm volatile("cp.async.wait_group 0;\n" ::: "memory");  // tile n ready
        __syncthreads();   // all see K/V(n); all finished Phase B(n-1)

        // Stage tile n+1 AFTER the barrier: its buffer (buf^1) was read by
        // Phase B(n-1), which every thread completed before this barrier.
        if (n + 1 < ntiles) {
            stage_tile(smf, tid, tbase + TILE, buf ^ 1, kh, vhh);
            asm volatile("cp.async.commit_group;\n" ::: "memory");
        }

        // ---- Phase A: scores from smem K. Half-warp per token, 2 passes.
        const float* Kb = SM_K(buf);
        #pragma unroll
        for (int pass = 0; pass < 2; ++pass) {
            const int tt = pass * 8 + hw;                // token in tile
            const float* kr = Kb + tt * DD + hl * 4;
            const float4 k0 = *(const float4*)kr;
            const float4 k1 = *(const float4*)(kr + 64);

            float s0 = q0[0].x*k0.x + q0[0].y*k0.y + q0[0].z*k0.z + q0[0].w*k0.w
                     + q1[0].x*k1.x + q1[0].y*k1.y + q1[0].z*k1.z + q1[0].w*k1.w;
            float s1 = q0[1].x*k0.x + q0[1].y*k0.y + q0[1].z*k0.z + q0[1].w*k0.w
                     + q1[1].x*k1.x + q1[1].y*k1.y + q1[1].z*k1.z + q1[1].w*k1.w;
            float s2 = q0[2].x*k0.x + q0[2].y*k0.y + q0[2].z*k0.z + q0[2].w*k0.w
                     + q1[2].x*k1.x + q1[2].y*k1.y + q1[2].z*k1.z + q1[2].w*k1.w;
            float s3 = q0[3].x*k0.x + q0[3].y*k0.y + q0[3].z*k0.z + q0[3].w*k0.w
                     + q1[3].x*k1.x + q1[3].y*k1.y + q1[3].z*k1.z + q1[3].w*k1.w;

            #pragma unroll
            for (int off = 8; off; off >>= 1) {
                s0 += __shfl_xor_sync(0xffffffffu, s0, off);
                s1 += __shfl_xor_sync(0xffffffffu, s1, off);
                s2 += __shfl_xor_sync(0xffffffffu, s2, off);
                s3 += __shfl_xor_sync(0xffffffffu, s3, off);
            }
            if (hl == 0) {
                float4* s4 = (float4*)SM_S;
                s4[tt] = (tt < nt) ? make_float4(s0 * SCALE_F, s1 * SCALE_F,
                                                 s2 * SCALE_F, s3 * SCALE_F)
                                   : make_float4(NEGINF, NEGINF, NEGINF, NEGINF);
            }
        }
        __syncthreads();   // sync1: s_s ready

        // ---- Online softmax: warp `wid` owns head `wid`. TILE=16, so both
        //      16-lane halves hold duplicate values; half-reductions give the
        //      full, warp-uniform max and sum.
        {
            const float xa = SM_S[hl * 4 + wid];
            float x = xa;
            #pragma unroll
            for (int off = 8; off; off >>= 1)
                x = fmaxf(x, __shfl_xor_sync(0xffffffffu, x, off));
            const float mn  = fmaxf(m_run, x);
            const float scl = __expf(m_run - mn);
            m_run = mn;
            if (lane == 0) SM_SC[wid] = scl;
            const float pa = __expf(xa - mn);
            if (half == 0) SM_P[hl * 4 + wid] = pa;
            float ps = pa;
            #pragma unroll
            for (int off = 8; off; off >>= 1)
                ps += __shfl_xor_sync(0xffffffffu, ps, off);
            l_run = l_run * scl + ps;
        }
        __syncthreads();   // sync2: p_s / sc_s ready

        // ---- Rescale + Phase B: thread tid owns dim d = tid for all 4 heads.
        const float c0 = SM_SC[0], c1 = SM_SC[1], c2 = SM_SC[2], c3 = SM_SC[3];
        acc0 *= c0; acc1 *= c1; acc2 *= c2; acc3 *= c3;

        const float4* p4s = (const float4*)SM_P;
        const float*  Vb  = SM_V(buf) + tid;
        #pragma unroll 8
        for (int j = 0; j < nt; ++j) {
            const float4 p4 = p4s[j];
            const float  v  = Vb[j * DD];
            acc0 += p4.x * v; acc1 += p4.y * v;
            acc2 += p4.z * v; acc3 += p4.w * v;
        }
        // No trailing barrier: the post-wait __syncthreads at the top of the
        // next iteration orders these reads before any buffer reuse.
    }

    if (lane == 0) { SM_MF[wid] = m_run; SM_LF[wid] = l_run; }
    __syncthreads();

    const float l0 = fmaxf(SM_LF[0], 1e-30f);
    const float l1 = fmaxf(SM_LF[1], 1e-30f);
    const float l2 = fmaxf(SM_LF[2], 1e-30f);
    const float l3 = fmaxf(SM_LF[3], 1e-30f);
    g_po[(pbase + 0) * DD + tid] = acc0 / l0;
    g_po[(pbase + 1) * DD + tid] = acc1 / l1;
    g_po[(pbase + 2) * DD + tid] = acc2 / l2;
    g_po[(pbase + 3) * DD + tid] = acc3 / l3;
    if (tid < GG)
        g_plse[pbase + tid] = SM_MF[tid] + __logf(fmaxf(SM_LF[tid], 1e-30f));
}

#define CTHREADS 512
#define NSLICE 16
#define PER_SLICE (RS / NSLICE)   // 8

__global__ void __launch_bounds__(CTHREADS)
combine_kernel(float* __restrict__ out)
{
    const int bh  = blockIdx.x;     // b*HQ + hq
    const int dq  = blockIdx.y;     // dim quarter 0..3
    const int tid = threadIdx.x;
    const int dl  = tid & 31;       // lane = dim within quarter
    const int sl  = tid >> 5;       // slice 0..15 (one warp each)
    const int d   = dq * 32 + dl;

    __shared__ float lse_s[RS];
    __shared__ float accs[NSLICE][32];
    __shared__ float wss[NSLICE];

    if (tid < RS)
        lse_s[tid] = g_plse[tid * (BB * HQ) + bh];
    __syncthreads();

    // Global max via warp reduce (4 LDS + 5 SHFL per warp).
    float gm;
    {
        float x = fmaxf(fmaxf(lse_s[dl], lse_s[dl + 32]),
                        fmaxf(lse_s[dl + 64], lse_s[dl + 96]));
        #pragma unroll
        for (int off = 16; off; off >>= 1)
            x = fmaxf(x, __shfl_xor_sync(0xffffffffu, x, off));
        gm = x;
    }

    // Each slice-warp accumulates its 8 partials for its 32 dims.
    float acc = 0.f, ws = 0.f;
    #pragma unroll
    for (int t = 0; t < PER_SLICE; ++t) {
        const int   i   = sl * PER_SLICE + t;
        const float lse = lse_s[i];
        if (lse > -5.0e29f) {
            const float w = __expf(lse - gm);
            ws  += w;
            acc += w * __ldg(&g_po[(i * (BB * HQ) + bh) * DD + d]);
        }
    }
    accs[sl][dl] = acc;
    if (dl == 0) wss[sl] = ws;
    __syncthreads();

    if (sl == 0) {
        float a = 0.f, wt = 0.f;
        #pragma unroll
        for (int k = 0; k < NSLICE; ++k) {
            a  += accs[k][dl];
            wt += wss[k];
        }
        out[bh * DD + d] = a / fmaxf(wt, 1e-30f);
    }
}

extern "C" void kernel_launch(void* const* d_in, const int* in_sizes, int n_in,
                              void* d_out, int out_size)
{
    (void)in_sizes; (void)n_in; (void)out_size;
    const float* q    = (const float*)d_in[0];
    const float* kc   = (const float*)d_in[1];
    const float* vc   = (const float*)d_in[2];
    const int*   lens = (const int*)d_in[3];
    const int*   bt   = (const int*)d_in[4];

    cudaFuncSetAttribute(decode_kernel,
                         cudaFuncAttributeMaxDynamicSharedMemorySize, SMEM_BYTES);

    dim3 grid1(NSPLIT, HKV, RR * BB);
    decode_kernel<<<grid1, 128, SMEM_BYTES>>>(q, kc, vc, lens, bt);
    dim3 grid2(BB * HQ, 4);
    combine_kernel<<<grid2, CTHREADS>>>((float*)d_out);
}

// round 12
// speedup vs baseline: 1.3411x; 1.0222x over previous
#include <cuda_runtime.h>

#define RR 8
#define BB 8
#define LL 2048
#define PP 16384
#define HQ 32
#define HKV 8
#define GG 4
#define DD 128
#define NSPLIT 16
#define CHUNK (LL / NSPLIT)   // 128
#define TILE 16
#define RS (RR * NSPLIT)      // 128 partials per (b, hq)
#define SCALE_F 0.08838834764831845f
#define NEGINF -1.0e30f
#define HD (HKV * DD)         // 1024 floats per page row

// Dynamic smem layout (float offsets):
//   [0    .. 4096)  Ks[2][TILE*DD]   (16KB)
//   [4096 .. 8192)  Vs[2][TILE*DD]   (16KB)
//   [8192 .. 8320)  pg_all (128 ints)
//   [8320 .. 8384)  s_s (TILE*4)
//   [8384 .. 8448)  p_s (TILE*4)
//   [8448 .. 8460)  sc, m_fin, l_fin
#define SM_K(s)   (smf + (s) * (TILE * DD))
#define SM_V(s)   (smf + 4096 + (s) * (TILE * DD))
#define SM_PG     ((int*)(smf + 8192))
#define SM_S      (smf + 8320)
#define SM_P      (smf + 8384)
#define SM_SC     (smf + 8448)
#define SM_MF     (smf + 8452)
#define SM_LF     (smf + 8456)
#define SMEM_BYTES (8460 * 4)

// Scratch for split-KV partials (device globals; no runtime allocation).
// g_po:   [i][bh][d]  (decode-write-friendly, combine reads 128B lines)
// g_plse: [bh][i]     (TRANSPOSED: combine reads one coalesced 512B row)
__device__ float g_po[RS * BB * HQ * DD];   // ~16.8MB
__device__ float g_plse[BB * HQ * RS];

// Stage one 16-token tile of K and V (8KB + 8KB) via cp.async.
// 512 chunks of 16B each; 4 K-chunks + 4 V-chunks per thread.
__device__ __forceinline__ void stage_tile(float* smf, int tid, int nbase,
                                           int bufi,
                                           const float* __restrict__ kh,
                                           const float* __restrict__ vhh)
{
    const unsigned kd = (unsigned)__cvta_generic_to_shared(SM_K(bufi));
    const unsigned vd = (unsigned)__cvta_generic_to_shared(SM_V(bufi));
    #pragma unroll
    for (int i = 0; i < 4; ++i) {
        const int c   = i * 128 + tid;    // 0..511 chunk id (16B)
        const int tok = c >> 5;           // 0..15
        const int off = (c & 31) << 2;    // float offset in row
        const long prow = (long)SM_PG[nbase + tok] * HD;
        const unsigned doff = (unsigned)((tok * DD + off) << 2);
        asm volatile("cp.async.cg.shared.global [%0], [%1], 16;\n"
                     :: "r"(kd + doff), "l"(kh + prow + off));
        asm volatile("cp.async.cg.shared.global [%0], [%1], 16;\n"
                     :: "r"(vd + doff), "l"(vhh + prow + off));
    }
}

__global__ void __launch_bounds__(128)
decode_kernel(const float* __restrict__ q,
              const float* __restrict__ kc,
              const float* __restrict__ vc,
              const int* __restrict__ lens,
              const int* __restrict__ bt)
{
    extern __shared__ float smf[];

    const int split = blockIdx.x;
    const int hkv   = blockIdx.y;
    const int rb    = blockIdx.z;          // r*BB + b
    const int r     = rb >> 3;
    const int b     = rb & 7;
    const int tid   = threadIdx.x;
    const int wid   = tid >> 5;            // 0..3  (warp == head for softmax)
    const int lane  = tid & 31;
    const int half  = lane >> 4;
    const int hl    = lane & 15;           // lane within half-warp
    const int hw    = wid * 2 + half;      // half-warp id 0..7

    const int kv_len = lens[rb];
    const int start  = split * CHUNK;
    const int end    = min(start + CHUNK, kv_len);
    const int rsplit = r * NSPLIT + split;            // partial index i
    const int pbase  = (rsplit * BB + b) * HQ + hkv * GG;
    const int lbase  = (b * HQ + hkv * GG) * RS + rsplit;

    if (end <= start) {
        if (tid < GG)
            g_plse[lbase + tid * RS] = NEGINF;
        return;
    }
    const int len    = end - start;                 // 1..128
    const int ntiles = (len + TILE - 1) / TILE;     // 1..8

    // Q into registers: head g, dims hl*4..+3 (lo) and 64+hl*4..+3 (hi).
    // Quarter-warp-contiguous mapping -> conflict-free LDS.128 in Phase A.
    const float* qb = q + (b * HQ + hkv * GG) * DD + hl * 4;
    float4 q0[GG], q1[GG];
    #pragma unroll
    for (int g = 0; g < GG; ++g) {
        q0[g] = *(const float4*)(qb + g * DD);
        q1[g] = *(const float4*)(qb + g * DD + 64);
    }

    const int*   btb = bt + rb * LL + start;
    const float* kh  = kc + (long)r * PP * HD + hkv * DD;
    const float* vhh = vc + (long)r * PP * HD + hkv * DD;

    // ---- Preload all pages for this chunk (one volley, page 0 for invalid).
    SM_PG[tid] = (tid < len) ? __ldg(btb + tid) : 0;
    __syncthreads();

    // ---- Prime: stage tile 0.
    stage_tile(smf, tid, 0, 0, kh, vhh);
    asm volatile("cp.async.commit_group;\n" ::: "memory");

    float acc0 = 0.f, acc1 = 0.f, acc2 = 0.f, acc3 = 0.f;
    float m_run = NEGINF, l_run = 0.f;

    for (int n = 0; n < ntiles; ++n) {
        const int buf   = n & 1;
        const int tbase = n * TILE;
        const int nt    = min(TILE, len - tbase);

        asm volatile("cp.async.wait_group 0;\n" ::: "memory");  // tile n ready
        __syncthreads();   // all see K/V(n); all finished Phase B(n-1)

        // Stage tile n+1 AFTER the barrier: its buffer (buf^1) was read by
        // Phase B(n-1), which every thread completed before this barrier.
        if (n + 1 < ntiles) {
            stage_tile(smf, tid, tbase + TILE, buf ^ 1, kh, vhh);
            asm volatile("cp.async.commit_group;\n" ::: "memory");
        }

        // ---- Phase A: scores from smem K. Half-warp per token, 2 passes.
        const float* Kb = SM_K(buf);
        #pragma unroll
        for (int pass = 0; pass < 2; ++pass) {
            const int tt = pass * 8 + hw;                // token in tile
            const float* kr = Kb + tt * DD + hl * 4;
            const float4 k0 = *(const float4*)kr;
            const float4 k1 = *(const float4*)(kr + 64);

            float s0 = q0[0].x*k0.x + q0[0].y*k0.y + q0[0].z*k0.z + q0[0].w*k0.w
                     + q1[0].x*k1.x + q1[0].y*k1.y + q1[0].z*k1.z + q1[0].w*k1.w;
            float s1 = q0[1].x*k0.x + q0[1].y*k0.y + q0[1].z*k0.z + q0[1].w*k0.w
                     + q1[1].x*k1.x + q1[1].y*k1.y + q1[1].z*k1.z + q1[1].w*k1.w;
            float s2 = q0[2].x*k0.x + q0[2].y*k0.y + q0[2].z*k0.z + q0[2].w*k0.w
                     + q1[2].x*k1.x + q1[2].y*k1.y + q1[2].z*k1.z + q1[2].w*k1.w;
            float s3 = q0[3].x*k0.x + q0[3].y*k0.y + q0[3].z*k0.z + q0[3].w*k0.w
                     + q1[3].x*k1.x + q1[3].y*k1.y + q1[3].z*k1.z + q1[3].w*k1.w;

            #pragma unroll
            for (int off = 8; off; off >>= 1) {
                s0 += __shfl_xor_sync(0xffffffffu, s0, off);
                s1 += __shfl_xor_sync(0xffffffffu, s1, off);
                s2 += __shfl_xor_sync(0xffffffffu, s2, off);
                s3 += __shfl_xor_sync(0xffffffffu, s3, off);
            }
            if (hl == 0) {
                float4* s4 = (float4*)SM_S;
                s4[tt] = (tt < nt) ? make_float4(s0 * SCALE_F, s1 * SCALE_F,
                                                 s2 * SCALE_F, s3 * SCALE_F)
                                   : make_float4(NEGINF, NEGINF, NEGINF, NEGINF);
            }
        }
        __syncthreads();   // sync1: s_s ready

        // ---- Online softmax: warp `wid` owns head `wid`. TILE=16, so both
        //      16-lane halves hold duplicate values; half-reductions give the
        //      full, warp-uniform max and sum.
        {
            const float xa = SM_S[hl * 4 + wid];
            float x = xa;
            #pragma unroll
            for (int off = 8; off; off >>= 1)
                x = fmaxf(x, __shfl_xor_sync(0xffffffffu, x, off));
            const float mn  = fmaxf(m_run, x);
            const float scl = __expf(m_run - mn);
            m_run = mn;
            if (lane == 0) SM_SC[wid] = scl;
            const float pa = __expf(xa - mn);
            if (half == 0) SM_P[hl * 4 + wid] = pa;
            float ps = pa;
            #pragma unroll
            for (int off = 8; off; off >>= 1)
                ps += __shfl_xor_sync(0xffffffffu, ps, off);
            l_run = l_run * scl + ps;
        }
        __syncthreads();   // sync2: p_s / sc_s ready

        // ---- Rescale + Phase B: thread tid owns dim d = tid for all 4 heads.
        const float c0 = SM_SC[0], c1 = SM_SC[1], c2 = SM_SC[2], c3 = SM_SC[3];
        acc0 *= c0; acc1 *= c1; acc2 *= c2; acc3 *= c3;

        const float4* p4s = (const float4*)SM_P;
        const float*  Vb  = SM_V(buf) + tid;
        #pragma unroll 8
        for (int j = 0; j < nt; ++j) {
            const float4 p4 = p4s[j];
            const float  v  = Vb[j * DD];
            acc0 += p4.x * v; acc1 += p4.y * v;
            acc2 += p4.z * v; acc3 += p4.w * v;
        }
        // No trailing barrier: the post-wait __syncthreads at the top of the
        // next iteration orders these reads before any buffer reuse.
    }

    if (lane == 0) { SM_MF[wid] = m_run; SM_LF[wid] = l_run; }
    __syncthreads();

    const float l0 = fmaxf(SM_LF[0], 1e-30f);
    const float l1 = fmaxf(SM_LF[1], 1e-30f);
    const float l2 = fmaxf(SM_LF[2], 1e-30f);
    const float l3 = fmaxf(SM_LF[3], 1e-30f);
    g_po[(pbase + 0) * DD + tid] = acc0 / l0;
    g_po[(pbase + 1) * DD + tid] = acc1 / l1;
    g_po[(pbase + 2) * DD + tid] = acc2 / l2;
    g_po[(pbase + 3) * DD + tid] = acc3 / l3;
    if (tid < GG)
        g_plse[lbase + tid * RS] =
            SM_MF[tid] + __logf(fmaxf(SM_LF[tid], 1e-30f));
}

#define CTHREADS 256
#define NSLICE 8
#define PER_SLICE (RS / NSLICE)   // 16

__global__ void __launch_bounds__(CTHREADS)
combine_kernel(float* __restrict__ out)
{
    const int bh  = blockIdx.x;     // b*HQ + hq
    const int dq  = blockIdx.y;     // dim quarter 0..3
    const int tid = threadIdx.x;
    const int dl  = tid & 31;       // lane = dim within quarter
    const int sl  = tid >> 5;       // slice-warp 0..7
    const int d   = dq * 32 + dl;

    __shared__ float lse_s[RS];
    __shared__ float accs[NSLICE][32];
    __shared__ float wss[NSLICE];

    if (tid < RS)
        lse_s[tid] = g_plse[bh * RS + tid];   // one coalesced 512B row
    __syncthreads();

    // Global max via warp reduce (4 LDS + 5 SHFL; warp-uniform result).
    float gm;
    {
        float x = fmaxf(fmaxf(lse_s[dl], lse_s[dl + 32]),
                        fmaxf(lse_s[dl + 64], lse_s[dl + 96]));
        #pragma unroll
        for (int off = 16; off; off >>= 1)
            x = fmaxf(x, __shfl_xor_sync(0xffffffffu, x, off));
        gm = x;
    }

    // Each slice-warp accumulates its 16 partials for its 32 dims;
    // fully unrolled so the predicated LDGs front-batch (MLP up to 16).
    float acc = 0.f, ws = 0.f;
    #pragma unroll
    for (int t = 0; t < PER_SLICE; ++t) {
        const int   i   = sl * PER_SLICE + t;
        const float lse = lse_s[i];
        if (lse > -5.0e29f) {
            const float w = __expf(lse - gm);
            ws  += w;
            acc += w * __ldg(&g_po[(i * (BB * HQ) + bh) * DD + d]);
        }
    }
    accs[sl][dl] = acc;
    if (dl == 0) wss[sl] = ws;
    __syncthreads();

    if (sl == 0) {
        float a = 0.f, wt = 0.f;
        #pragma unroll
        for (int k = 0; k < NSLICE; ++k) {
            a  += accs[k][dl];
            wt += wss[k];
        }
        out[bh * DD + d] = a / fmaxf(wt, 1e-30f);
    }
}

extern "C" void kernel_launch(void* const* d_in, const int* in_sizes, int n_in,
                              void* d_out, int out_size)
{
    (void)in_sizes; (void)n_in; (void)out_size;
    const float* q    = (const float*)d_in[0];
    const float* kc   = (const float*)d_in[1];
    const float* vc   = (const float*)d_in[2];
    const int*   lens = (const int*)d_in[3];
    const int*   bt   = (const int*)d_in[4];

    cudaFuncSetAttribute(decode_kernel,
                         cudaFuncAttributeMaxDynamicSharedMemorySize, SMEM_BYTES);

    dim3 grid1(NSPLIT, HKV, RR * BB);
    decode_kernel<<<grid1, 128, SMEM_BYTES>>>(q, kc, vc, lens, bt);
    dim3 grid2(BB * HQ, 4);
    combine_kernel<<<grid2, CTHREADS>>>((float*)d_out);
}